// round 2
// baseline (speedup 1.0000x reference)
#include <cuda_runtime.h>
#include <math.h>

// ---------------------------------------------------------------------------
// PrisonerDilemmaEngine — fp32 SIMT baseline (R2: partitionable threefry)
// N=131072 cells, IN=128, HID=256, OUT=128, MLP=128, 8 factions (fs=16384, dc=4096)
// ---------------------------------------------------------------------------

#define NCELLS 131072
#define FS     16384
#define DC     4096

// scratch (device globals — no allocation inside kernel_launch)
__device__ float g_H1[(size_t)NCELLS * 256];   // relu(layer1) for a|g
__device__ float g_out[(size_t)NCELLS * 128];  // a - g
__device__ float g_tension[NCELLS];
__device__ float g_G1[(size_t)NCELLS * 768];   // gh = hiddens @ whh^T + bhh
__device__ float g_G2[(size_t)NCELLS * 768];   // gi = memin   @ wih^T + bih
__device__ float g_newh[(size_t)NCELLS * 256]; // post-GRU, payoff-scaled, clamped
__device__ float g_xwb[256];                   // x-part of layer1 + bias (rank-1)
__device__ float g_fsum[2048];                 // per-faction sums of newh   [8][256]
__device__ float g_fdcsum[2048];               // per-faction debate-cell sums
__device__ float g_fmean[2048];
__device__ float g_globalop[256];
__device__ float g_gmean[256];
__device__ float g_sumexp;
__device__ float g_sumtens;
__device__ float g_sumexpout[128];

// ---------------------------------------------------------------------------
// K0: zero accumulators + precompute xwb[r] = b1[r] + sum_k x[k]*W1[r][k<128]
// ---------------------------------------------------------------------------
__global__ void k0_init(const float* __restrict__ x,
                        const float* __restrict__ a_w1, const float* __restrict__ a_b1,
                        const float* __restrict__ g_w1, const float* __restrict__ g_b1) {
    int tid = threadIdx.x;
    if (tid == 0) { g_sumexp = 0.f; g_sumtens = 0.f; }
    if (tid < 128) g_sumexpout[tid] = 0.f;
    for (int k = tid; k < 2048; k += 256) { g_fsum[k] = 0.f; g_fdcsum[k] = 0.f; }
    // xwb
    int r = tid;
    const float* w = (r < 128) ? (a_w1 + (size_t)r * 384)
                               : (g_w1 + (size_t)(r - 128) * 384);
    float s = (r < 128) ? a_b1[r] : g_b1[r - 128];
    #pragma unroll 4
    for (int k = 0; k < 128; k++) s += x[k] * w[k];
    g_xwb[r] = s;
}

// ---------------------------------------------------------------------------
// shared GEMM tile geometry: BM=128 cells, BN=128 cols, BK=16, 256 threads,
// 8x8 register tile per thread
// ---------------------------------------------------------------------------
#define GEMM_INNER(As, Ws, acc)                                              \
    _Pragma("unroll")                                                        \
    for (int kk = 0; kk < 16; kk++) {                                        \
        float af[8], wf[8];                                                  \
        *(float4*)(af)     = *(const float4*)&As[kk][ty * 8];                \
        *(float4*)(af + 4) = *(const float4*)&As[kk][ty * 8 + 4];            \
        *(float4*)(wf)     = *(const float4*)&Ws[kk][tx * 8];                \
        *(float4*)(wf + 4) = *(const float4*)&Ws[kk][tx * 8 + 4];            \
        _Pragma("unroll")                                                    \
        for (int i = 0; i < 8; i++)                                          \
            _Pragma("unroll")                                                \
            for (int j = 0; j < 8; j++) acc[i][j] += af[i] * wf[j];          \
    }

// ---------------------------------------------------------------------------
// K1: H1 = relu(hiddens @ W1h^T + xwb), W1h = [a_w1 | g_w1][:,128:384], M=256
// grid (1024, 2)
// ---------------------------------------------------------------------------
__global__ void __launch_bounds__(256) k1_layer1(const float* __restrict__ hiddens,
                                                 const float* __restrict__ a_w1,
                                                 const float* __restrict__ g_w1) {
    __shared__ float As[16][128];
    __shared__ float Ws[16][128];
    const int tid = threadIdx.x;
    const int tx = tid & 15, ty = tid >> 4;
    const int c0 = blockIdx.x * 128;
    const int m0 = blockIdx.y * 128;
    float acc[8][8];
    #pragma unroll
    for (int i = 0; i < 8; i++)
        #pragma unroll
        for (int j = 0; j < 8; j++) acc[i][j] = 0.f;

    const int arow = tid >> 1;
    const int ak = (tid & 1) * 8;
    const int r = m0 + arow;
    const float* wbase = (r < 128) ? (a_w1 + (size_t)r * 384 + 128)
                                   : (g_w1 + (size_t)(r - 128) * 384 + 128);
    const float* abase = hiddens + (size_t)(c0 + arow) * 256;

    for (int k0 = 0; k0 < 256; k0 += 16) {
        float4 a0 = *(const float4*)(abase + k0 + ak);
        float4 a1 = *(const float4*)(abase + k0 + ak + 4);
        float4 w0 = *(const float4*)(wbase + k0 + ak);
        float4 w1 = *(const float4*)(wbase + k0 + ak + 4);
        As[ak + 0][arow] = a0.x; As[ak + 1][arow] = a0.y; As[ak + 2][arow] = a0.z; As[ak + 3][arow] = a0.w;
        As[ak + 4][arow] = a1.x; As[ak + 5][arow] = a1.y; As[ak + 6][arow] = a1.z; As[ak + 7][arow] = a1.w;
        Ws[ak + 0][arow] = w0.x; Ws[ak + 1][arow] = w0.y; Ws[ak + 2][arow] = w0.z; Ws[ak + 3][arow] = w0.w;
        Ws[ak + 4][arow] = w1.x; Ws[ak + 5][arow] = w1.y; Ws[ak + 6][arow] = w1.z; Ws[ak + 7][arow] = w1.w;
        __syncthreads();
        GEMM_INNER(As, Ws, acc)
        __syncthreads();
    }
    #pragma unroll
    for (int i = 0; i < 8; i++) {
        int row = c0 + ty * 8 + i;
        #pragma unroll
        for (int j = 0; j < 8; j++) {
            int col = m0 + tx * 8 + j;
            float v = acc[i][j] + g_xwb[col];
            g_H1[(size_t)row * 256 + col] = fmaxf(v, 0.f);
        }
    }
}

// ---------------------------------------------------------------------------
// K2: out = H1 @ [a_w2 | -g_w2]^T + (a_b2 - g_b2); tension; softmax accumulators
// grid (1024)
// ---------------------------------------------------------------------------
__global__ void __launch_bounds__(256) k2_layer2(const float* __restrict__ a_w2,
                                                 const float* __restrict__ g_w2,
                                                 const float* __restrict__ a_b2,
                                                 const float* __restrict__ g_b2) {
    __shared__ float As[16][128];
    __shared__ float Ws[16][128];
    __shared__ float s_wout[128];
    __shared__ float s_scal[2];
    const int tid = threadIdx.x;
    const int tx = tid & 15, ty = tid >> 4;
    const int c0 = blockIdx.x * 128;
    float acc[8][8];
    #pragma unroll
    for (int i = 0; i < 8; i++)
        #pragma unroll
        for (int j = 0; j < 8; j++) acc[i][j] = 0.f;

    const int arow = tid >> 1;
    const int ak = (tid & 1) * 8;
    const float* abase = g_H1 + (size_t)(c0 + arow) * 256;

    for (int k0 = 0; k0 < 256; k0 += 16) {
        int kw = k0 + ak;
        float4 a0 = *(const float4*)(abase + kw);
        float4 a1 = *(const float4*)(abase + kw + 4);
        float4 w0, w1;
        if (kw < 128) {
            const float* p = a_w2 + (size_t)arow * 128 + kw;
            w0 = *(const float4*)p; w1 = *(const float4*)(p + 4);
        } else {
            const float* p = g_w2 + (size_t)arow * 128 + (kw - 128);
            w0 = *(const float4*)p; w1 = *(const float4*)(p + 4);
            w0.x = -w0.x; w0.y = -w0.y; w0.z = -w0.z; w0.w = -w0.w;
            w1.x = -w1.x; w1.y = -w1.y; w1.z = -w1.z; w1.w = -w1.w;
        }
        As[ak + 0][arow] = a0.x; As[ak + 1][arow] = a0.y; As[ak + 2][arow] = a0.z; As[ak + 3][arow] = a0.w;
        As[ak + 4][arow] = a1.x; As[ak + 5][arow] = a1.y; As[ak + 6][arow] = a1.z; As[ak + 7][arow] = a1.w;
        Ws[ak + 0][arow] = w0.x; Ws[ak + 1][arow] = w0.y; Ws[ak + 2][arow] = w0.z; Ws[ak + 3][arow] = w0.w;
        Ws[ak + 4][arow] = w1.x; Ws[ak + 5][arow] = w1.y; Ws[ak + 6][arow] = w1.z; Ws[ak + 7][arow] = w1.w;
        __syncthreads();
        GEMM_INNER(As, Ws, acc)
        __syncthreads();
    }

    if (tid < 128) s_wout[tid] = 0.f;
    if (tid < 2) s_scal[tid] = 0.f;
    __syncthreads();

    float wr[8], tr[8];
    #pragma unroll
    for (int i = 0; i < 8; i++) {
        int row = c0 + ty * 8 + i;
        float s = 0.f;
        #pragma unroll
        for (int j = 0; j < 8; j++) {
            int col = tx * 8 + j;
            float v = acc[i][j] + a_b2[col] - g_b2[col];
            acc[i][j] = v;
            s += v * v;
        }
        #pragma unroll
        for (int o = 8; o > 0; o >>= 1) s += __shfl_xor_sync(0xffffffffu, s, o, 16);
        float t = s * 0.0078125f;  // /128
        tr[i] = t;
        wr[i] = expf(t);
        if (tx == 0) g_tension[row] = t;
        float4 o0 = make_float4(acc[i][0], acc[i][1], acc[i][2], acc[i][3]);
        float4 o1 = make_float4(acc[i][4], acc[i][5], acc[i][6], acc[i][7]);
        *(float4*)&g_out[(size_t)row * 128 + tx * 8] = o0;
        *(float4*)&g_out[(size_t)row * 128 + tx * 8 + 4] = o1;
    }
    #pragma unroll
    for (int j = 0; j < 8; j++) {
        float pw = 0.f;
        #pragma unroll
        for (int i = 0; i < 8; i++) pw += wr[i] * acc[i][j];
        atomicAdd(&s_wout[tx * 8 + j], pw);
    }
    if (tx == 0) {
        float se = 0.f, st = 0.f;
        #pragma unroll
        for (int i = 0; i < 8; i++) { se += wr[i]; st += tr[i]; }
        atomicAdd(&s_scal[0], se);
        atomicAdd(&s_scal[1], st);
    }
    __syncthreads();
    if (tid < 128) atomicAdd(&g_sumexpout[tid], s_wout[tid]);
    if (tid == 0) { atomicAdd(&g_sumexp, s_scal[0]); atomicAdd(&g_sumtens, s_scal[1]); }
}

// ---------------------------------------------------------------------------
// K3a: G1 = hiddens @ gru_whh^T + bhh  (M=768, K=256), grid (1024, 6)
// ---------------------------------------------------------------------------
__global__ void __launch_bounds__(256) k3a_gh(const float* __restrict__ hiddens,
                                              const float* __restrict__ whh,
                                              const float* __restrict__ bhh) {
    __shared__ float As[16][128];
    __shared__ float Ws[16][128];
    const int tid = threadIdx.x;
    const int tx = tid & 15, ty = tid >> 4;
    const int c0 = blockIdx.x * 128;
    const int m0 = blockIdx.y * 128;
    float acc[8][8];
    #pragma unroll
    for (int i = 0; i < 8; i++)
        #pragma unroll
        for (int j = 0; j < 8; j++) acc[i][j] = 0.f;

    const int arow = tid >> 1;
    const int ak = (tid & 1) * 8;
    const float* wbase = whh + (size_t)(m0 + arow) * 256;
    const float* abase = hiddens + (size_t)(c0 + arow) * 256;

    for (int k0 = 0; k0 < 256; k0 += 16) {
        float4 a0 = *(const float4*)(abase + k0 + ak);
        float4 a1 = *(const float4*)(abase + k0 + ak + 4);
        float4 w0 = *(const float4*)(wbase + k0 + ak);
        float4 w1 = *(const float4*)(wbase + k0 + ak + 4);
        As[ak + 0][arow] = a0.x; As[ak + 1][arow] = a0.y; As[ak + 2][arow] = a0.z; As[ak + 3][arow] = a0.w;
        As[ak + 4][arow] = a1.x; As[ak + 5][arow] = a1.y; As[ak + 6][arow] = a1.z; As[ak + 7][arow] = a1.w;
        Ws[ak + 0][arow] = w0.x; Ws[ak + 1][arow] = w0.y; Ws[ak + 2][arow] = w0.z; Ws[ak + 3][arow] = w0.w;
        Ws[ak + 4][arow] = w1.x; Ws[ak + 5][arow] = w1.y; Ws[ak + 6][arow] = w1.z; Ws[ak + 7][arow] = w1.w;
        __syncthreads();
        GEMM_INNER(As, Ws, acc)
        __syncthreads();
    }
    #pragma unroll
    for (int i = 0; i < 8; i++) {
        int row = c0 + ty * 8 + i;
        #pragma unroll
        for (int j = 0; j < 8; j++) {
            int col = m0 + tx * 8 + j;
            g_G1[(size_t)row * 768 + col] = acc[i][j] + bhh[col];
        }
    }
}

// ---------------------------------------------------------------------------
// K3b: G2 = [out | tension] @ gru_wih^T + bih  (M=768, K=129), grid (1024, 6)
// ---------------------------------------------------------------------------
__global__ void __launch_bounds__(256) k3b_gi(const float* __restrict__ wih,
                                              const float* __restrict__ bih) {
    __shared__ float As[16][128];
    __shared__ float Ws[16][128];
    const int tid = threadIdx.x;
    const int tx = tid & 15, ty = tid >> 4;
    const int c0 = blockIdx.x * 128;
    const int m0 = blockIdx.y * 128;
    float acc[8][8];
    #pragma unroll
    for (int i = 0; i < 8; i++)
        #pragma unroll
        for (int j = 0; j < 8; j++) acc[i][j] = 0.f;

    const int arow = tid >> 1;
    const int ak = (tid & 1) * 8;
    const int r = m0 + arow;
    const int grow = c0 + arow;

    for (int k0 = 0; k0 < 129; k0 += 16) {
        #pragma unroll
        for (int u = 0; u < 8; u++) {
            int kw = k0 + ak + u;
            float av = 0.f, wv = 0.f;
            if (kw < 128)      av = g_out[(size_t)grow * 128 + kw];
            else if (kw == 128) av = g_tension[grow];
            if (kw < 129)      wv = wih[(size_t)r * 129 + kw];
            As[ak + u][arow] = av;
            Ws[ak + u][arow] = wv;
        }
        __syncthreads();
        GEMM_INNER(As, Ws, acc)
        __syncthreads();
    }
    #pragma unroll
    for (int i = 0; i < 8; i++) {
        int row = c0 + ty * 8 + i;
        #pragma unroll
        for (int j = 0; j < 8; j++) {
            int col = m0 + tx * 8 + j;
            g_G2[(size_t)row * 768 + col] = acc[i][j] + bih[col];
        }
    }
}

// ---------------------------------------------------------------------------
// K3c: GRU gates -> newh (payoff-scaled, clamped) + faction sum accumulators
// ---------------------------------------------------------------------------
__device__ __forceinline__ float sigmoidf_(float x) { return 1.f / (1.f + expf(-x)); }

__global__ void __launch_bounds__(256) k3c_gates(const float* __restrict__ hiddens,
                                                 const float* __restrict__ payoffs) {
    const int c0 = blockIdx.x * 128;
    const int j = threadIdx.x;
    const int f = c0 >> 14;
    const bool is_dc = (c0 & (FS - 1)) < DC;
    float lsum = 0.f;
    for (int ii = 0; ii < 128; ii++) {
        int i = c0 + ii;
        size_t b = (size_t)i * 768;
        float gi_r = g_G2[b + j],        gh_r = g_G1[b + j];
        float gi_z = g_G2[b + 256 + j],  gh_z = g_G1[b + 256 + j];
        float gi_n = g_G2[b + 512 + j],  gh_n = g_G1[b + 512 + j];
        float rg = sigmoidf_(gi_r + gh_r);
        float zg = sigmoidf_(gi_z + gh_z);
        float ng = tanhf(gi_n + rg * gh_n);
        float h = hiddens[(size_t)i * 256 + j];
        float v = (1.f - zg) * ng + zg * h;
        v *= (0.9f + 0.02f * payoffs[i]);
        v = fminf(fmaxf(v, -10.f), 10.f);
        g_newh[(size_t)i * 256 + j] = v;
        lsum += v;
    }
    atomicAdd(&g_fsum[f * 256 + j], lsum);
    if (is_dc) atomicAdd(&g_fdcsum[f * 256 + j], lsum);
}

// ---------------------------------------------------------------------------
// K4: faction means, global_op, analytic gmean, combined/pred, avg_tension
// ---------------------------------------------------------------------------
__global__ void k4_small(const int* __restrict__ step,
                         const float* __restrict__ head_w,
                         const float* __restrict__ head_b,
                         float* __restrict__ out) {
    const int j = threadIdx.x;
    float fs[8], fm[8];
    float gop = 0.f, total = 0.f;
    #pragma unroll
    for (int f = 0; f < 8; f++) {
        fs[f] = g_fsum[f * 256 + j];
        fm[f] = fs[f] * (1.f / 16384.f);
        gop += fm[f];
        total += fs[f];
    }
    gop *= 0.125f;
    if (*step > 5) {
        #pragma unroll
        for (int f = 0; f < 8; f++) {
            float ssdc = 0.85f * g_fdcsum[f * 256 + j] + 0.15f * 4096.f * fm[f];
            total += 0.15f * (4096.f * gop - ssdc);
        }
    }
    g_gmean[j] = total * (1.f / 131072.f);
    g_globalop[j] = gop;
    #pragma unroll
    for (int f = 0; f < 8; f++) g_fmean[f * 256 + j] = fm[f];

    if (j < 128) {
        float inv = 1.0f / g_sumexp;
        float a = head_b[j];
        #pragma unroll 4
        for (int q = 0; q < 128; q++) a += head_w[(size_t)j * 128 + q] * (g_sumexpout[q] * inv);
        out[j] = a;
    }
    if (j == 0) out[128] = g_sumtens * (1.f / 131072.f);
}

// ---------------------------------------------------------------------------
// threefry2x32 "partitionable" mode (JAX >= 0.5 default):
// per flat element e (uint64 < 2^32 here): counter = (hi32(e), lo32(e)) = (0, e)
// key = (0, 42); bits = out0 ^ out1 -> uniform -> sqrt(2)*erfinv
// ---------------------------------------------------------------------------
__device__ __forceinline__ float threefry_normal(unsigned e) {
    unsigned x0 = 0u, x1 = e;
    const unsigned ks0 = 0u, ks1 = 42u, ks2 = 0u ^ 42u ^ 0x1BD11BDAu;
    x0 += ks0; x1 += ks1;
#define TF_ROT(v, r) (((v) << (r)) | ((v) >> (32 - (r))))
#define TF_R4(a, b, c, d)                                        \
    x0 += x1; x1 = TF_ROT(x1, a); x1 ^= x0;                      \
    x0 += x1; x1 = TF_ROT(x1, b); x1 ^= x0;                      \
    x0 += x1; x1 = TF_ROT(x1, c); x1 ^= x0;                      \
    x0 += x1; x1 = TF_ROT(x1, d); x1 ^= x0;
    TF_R4(13, 15, 26, 6);  x0 += ks1; x1 += ks2 + 1u;
    TF_R4(17, 29, 16, 24); x0 += ks2; x1 += ks0 + 2u;
    TF_R4(13, 15, 26, 6);  x0 += ks0; x1 += ks1 + 3u;
    TF_R4(17, 29, 16, 24); x0 += ks1; x1 += ks2 + 4u;
    TF_R4(13, 15, 26, 6);  x0 += ks2; x1 += ks0 + 5u;
#undef TF_R4
#undef TF_ROT
    unsigned bits = x0 ^ x1;
    unsigned fb = (bits >> 9) | 0x3F800000u;
    float f01 = __uint_as_float(fb) - 1.0f;
    const float lo = -0.99999994f;            // nextafter(-1, 0)
    float u = f01 * 2.0f + lo;                // (hi - lo) rounds to 2.0f in fp32
    u = fmaxf(u, lo);
    return 1.4142135f * erfinvf(u);
}

// ---------------------------------------------------------------------------
// K5: faction sync + debate + coop pull + noise + clamp -> output new_hiddens
// ---------------------------------------------------------------------------
__global__ void __launch_bounds__(256) k5_final(const int* __restrict__ last_action,
                                                const int* __restrict__ step,
                                                float* __restrict__ out) {
    const int i = blockIdx.x;
    const int j = threadIdx.x;
    float v = g_newh[(size_t)i * 256 + j];
    const int f = i >> 14;
    v = 0.85f * v + 0.15f * g_fmean[f * 256 + j];
    if (*step > 5 && (i & (FS - 1)) < DC)
        v = 0.85f * v + 0.15f * g_globalop[j];
    float coop = (float)last_action[i];
    v += 0.05f * coop * (g_gmean[j] - v);
    unsigned e = (unsigned)i * 256u + (unsigned)j;
    float nz = threefry_normal(e);
    v += 0.02f * (1.0f - coop) * nz;
    v = fminf(fmaxf(v, -10.f), 10.f);
    out[129 + (size_t)i * 256 + j] = v;
}

// ---------------------------------------------------------------------------
extern "C" void kernel_launch(void* const* d_in, const int* in_sizes, int n_in,
                              void* d_out, int out_size) {
    const float* x        = (const float*)d_in[0];
    const float* payoffs  = (const float*)d_in[1];
    const int*   last_act = (const int*)d_in[2];
    const int*   step     = (const int*)d_in[3];
    const float* hiddens  = (const float*)d_in[4];
    const float* a_w1 = (const float*)d_in[5];
    const float* a_b1 = (const float*)d_in[6];
    const float* a_w2 = (const float*)d_in[7];
    const float* a_b2 = (const float*)d_in[8];
    const float* g_w1 = (const float*)d_in[9];
    const float* g_b1 = (const float*)d_in[10];
    const float* g_w2 = (const float*)d_in[11];
    const float* g_b2 = (const float*)d_in[12];
    const float* gru_wih = (const float*)d_in[13];
    const float* gru_whh = (const float*)d_in[14];
    const float* gru_bih = (const float*)d_in[15];
    const float* gru_bhh = (const float*)d_in[16];
    const float* head_w  = (const float*)d_in[17];
    const float* head_b  = (const float*)d_in[18];
    float* out = (float*)d_out;

    k0_init<<<1, 256>>>(x, a_w1, a_b1, g_w1, g_b1);
    k1_layer1<<<dim3(NCELLS / 128, 2), 256>>>(hiddens, a_w1, g_w1);
    k2_layer2<<<NCELLS / 128, 256>>>(a_w2, g_w2, a_b2, g_b2);
    k3a_gh<<<dim3(NCELLS / 128, 6), 256>>>(hiddens, gru_whh, gru_bhh);
    k3b_gi<<<dim3(NCELLS / 128, 6), 256>>>(gru_wih, gru_bih);
    k3c_gates<<<NCELLS / 128, 256>>>(hiddens, payoffs);
    k4_small<<<1, 256>>>(step, head_w, head_b, out);
    k5_final<<<NCELLS, 256>>>(last_act, step, out);
}

// round 4
// speedup vs baseline: 1.3497x; 1.3497x over previous
#include <cuda_runtime.h>
#include <cuda_bf16.h>
#include <math.h>

// ---------------------------------------------------------------------------
// PrisonerDilemmaEngine — R3: GEMMs on tensor pipe (mma.sync bf16 hi/lo split)
// N=131072 cells, IN=128, HID=256, OUT=128, MLP=128, 8 factions
// ---------------------------------------------------------------------------

#define NCELLS 131072
#define FS     16384
#define DC     4096

__device__ __align__(16) float g_H1[(size_t)NCELLS * 256];
__device__ __align__(16) float g_out[(size_t)NCELLS * 128];
__device__ __align__(16) float g_tension[NCELLS];
__device__ __align__(16) float g_G1[(size_t)NCELLS * 768];
__device__ __align__(16) float g_G2[(size_t)NCELLS * 768];
__device__ __align__(16) float g_newh[(size_t)NCELLS * 256];
__device__ float g_xwb[256];
__device__ float g_fsum[2048];
__device__ float g_fdcsum[2048];
__device__ float g_fmean[2048];
__device__ float g_globalop[256];
__device__ float g_gmean[256];
__device__ float g_sumexp;
__device__ float g_sumtens;
__device__ float g_sumexpout[128];

// ---------------------------------------------------------------------------
// K0: zero accumulators + xwb[r] = b1[r] + sum_k x[k]*W1[r][k<128]
// ---------------------------------------------------------------------------
__global__ void k0_init(const float* __restrict__ x,
                        const float* __restrict__ a_w1, const float* __restrict__ a_b1,
                        const float* __restrict__ g_w1, const float* __restrict__ g_b1) {
    int tid = threadIdx.x;
    if (tid == 0) { g_sumexp = 0.f; g_sumtens = 0.f; }
    if (tid < 128) g_sumexpout[tid] = 0.f;
    for (int k = tid; k < 2048; k += 256) { g_fsum[k] = 0.f; g_fdcsum[k] = 0.f; }
    int r = tid;
    const float* w = (r < 128) ? (a_w1 + (size_t)r * 384)
                               : (g_w1 + (size_t)(r - 128) * 384);
    float s = (r < 128) ? a_b1[r] : g_b1[r - 128];
    #pragma unroll 4
    for (int k = 0; k < 128; k++) s += x[k] * w[k];
    g_xwb[r] = s;
}

// ---------------------------------------------------------------------------
// MMA helpers
// ---------------------------------------------------------------------------
__device__ __forceinline__ unsigned sptr(const void* p) {
    return (unsigned)__cvta_generic_to_shared(p);
}

#define LDSM4(r0, r1, r2, r3, addr)                                           \
    asm volatile("ldmatrix.sync.aligned.m8n8.x4.shared.b16 {%0,%1,%2,%3}, [%4];" \
                 : "=r"(r0), "=r"(r1), "=r"(r2), "=r"(r3) : "r"(addr))

#define MMA_BF16(d, a, b0_, b1_)                                              \
    asm volatile("mma.sync.aligned.m16n8k16.row.col.f32.bf16.bf16.f32 "       \
                 "{%0,%1,%2,%3},{%4,%5,%6,%7},{%8,%9},{%0,%1,%2,%3};"         \
                 : "+f"(d[0]), "+f"(d[1]), "+f"(d[2]), "+f"(d[3])             \
                 : "r"(a[0]), "r"(a[1]), "r"(a[2]), "r"(a[3]),                \
                   "r"(b0_), "r"(b1_))

// ---------------------------------------------------------------------------
// Unified NT-GEMM on tensor pipe, hi/lo bf16 split (3-term), fp32 accum.
// C[cell 128-tile][col 128-tile] = A[cells][K] x W[cols][K]^T + epilogue(KID)
// KID: 1=k1(layer1)  2=k2(layer2+tension+softmax)  3=gh  4=gi
// block 256 thr = 8 warps; warp tile = 16 cells x 128 cols; K-chunk 32
// ---------------------------------------------------------------------------
template <int KID>
__global__ void __launch_bounds__(256) gemm_mma(
    const float* __restrict__ Aact,
    const float* __restrict__ W0, const float* __restrict__ W1,
    const float* __restrict__ B0, const float* __restrict__ B1) {
    __shared__ __nv_bfloat16 sAh[128][40], sAl[128][40];
    __shared__ __nv_bfloat16 sBh[128][40], sBl[128][40];
    __shared__ float s_b[128];
    __shared__ float s_wcol[128];
    __shared__ float s_wout[128];
    __shared__ float s_scal[2];

    const int tid = threadIdx.x, lane = tid & 31, warp = tid >> 5;
    const int c0 = blockIdx.x * 128, m0 = blockIdx.y * 128;
    constexpr int KDIM = (KID == 4) ? 128 : 256;

    if (tid < 128) {
        if (KID == 1) s_b[tid] = g_xwb[m0 + tid];
        if (KID == 2) s_b[tid] = B0[tid] - B1[tid];
        if (KID == 3) s_b[tid] = B0[m0 + tid];
        if (KID == 4) {
            s_b[tid] = B0[m0 + tid];
            s_wcol[tid] = W0[(size_t)(m0 + tid) * 129 + 128];
        }
        if (KID == 2) s_wout[tid] = 0.f;
    }
    if (KID == 2 && tid < 2) s_scal[tid] = 0.f;

    float acc[16][4];
    #pragma unroll
    for (int i = 0; i < 16; i++)
        #pragma unroll
        for (int j = 0; j < 4; j++) acc[i][j] = 0.f;

    const int arow = tid >> 1, ak = (tid & 1) * 16;

    const float* abase;
    if (KID == 2)      abase = g_H1  + (size_t)(c0 + arow) * 256;
    else if (KID == 4) abase = g_out + (size_t)(c0 + arow) * 128;
    else               abase = Aact  + (size_t)(c0 + arow) * 256;

    // ldmatrix lane addressing (x4, non-trans)
    const int l8 = lane & 7, grp = lane >> 3;
    const int am  = warp * 16 + l8 + ((grp & 1) << 3);  // A row
    const int ac8 = (grp & 2) << 2;                     // A +8 k
    const int bn  = l8 + ((grp & 2) << 2);              // B row (within 16-pair)
    const int bc8 = (grp & 1) << 3;                     // B +8 k

    for (int k0 = 0; k0 < KDIM; k0 += 32) {
        float av[16], wv[16];
        {
            const float4* ap = (const float4*)(abase + k0 + ak);
            *(float4*)(av + 0)  = ap[0]; *(float4*)(av + 4)  = ap[1];
            *(float4*)(av + 8)  = ap[2]; *(float4*)(av + 12) = ap[3];
        }
        if (KID == 1) {
            const float* wr_ = (blockIdx.y == 0 ? W0 : W1) + (size_t)arow * 384 + 128 + k0 + ak;
            const float4* wp = (const float4*)wr_;
            *(float4*)(wv + 0)  = wp[0]; *(float4*)(wv + 4)  = wp[1];
            *(float4*)(wv + 8)  = wp[2]; *(float4*)(wv + 12) = wp[3];
        } else if (KID == 2) {
            int kk = k0 + ak;
            bool neg = kk >= 128;
            const float* wr_ = neg ? (W1 + (size_t)arow * 128 + (kk - 128))
                                   : (W0 + (size_t)arow * 128 + kk);
            const float4* wp = (const float4*)wr_;
            *(float4*)(wv + 0)  = wp[0]; *(float4*)(wv + 4)  = wp[1];
            *(float4*)(wv + 8)  = wp[2]; *(float4*)(wv + 12) = wp[3];
            if (neg) {
                #pragma unroll
                for (int u = 0; u < 16; u++) wv[u] = -wv[u];
            }
        } else if (KID == 3) {
            const float* wr_ = W0 + (size_t)(m0 + arow) * 256 + k0 + ak;
            const float4* wp = (const float4*)wr_;
            *(float4*)(wv + 0)  = wp[0]; *(float4*)(wv + 4)  = wp[1];
            *(float4*)(wv + 8)  = wp[2]; *(float4*)(wv + 12) = wp[3];
        } else {
            const float* wr_ = W0 + (size_t)(m0 + arow) * 129 + k0 + ak;
            #pragma unroll
            for (int u = 0; u < 16; u++) wv[u] = wr_[u];
        }

        __syncthreads();
        #pragma unroll
        for (int u = 0; u < 16; u++) {
            float v = av[u];
            __nv_bfloat16 h = __float2bfloat16(v);
            sAh[arow][ak + u] = h;
            sAl[arow][ak + u] = __float2bfloat16(v - __bfloat162float(h));
            v = wv[u];
            h = __float2bfloat16(v);
            sBh[arow][ak + u] = h;
            sBl[arow][ak + u] = __float2bfloat16(v - __bfloat162float(h));
        }
        __syncthreads();

        #pragma unroll
        for (int kh = 0; kh < 2; kh++) {
            const int kk = kh * 16;
            unsigned ah[4], al[4];
            LDSM4(ah[0], ah[1], ah[2], ah[3], sptr(&sAh[am][kk + ac8]));
            LDSM4(al[0], al[1], al[2], al[3], sptr(&sAl[am][kk + ac8]));
            #pragma unroll
            for (int p = 0; p < 8; p++) {
                unsigned bh[4], bl[4];
                LDSM4(bh[0], bh[1], bh[2], bh[3], sptr(&sBh[p * 16 + bn][kk + bc8]));
                LDSM4(bl[0], bl[1], bl[2], bl[3], sptr(&sBl[p * 16 + bn][kk + bc8]));
                MMA_BF16(acc[2 * p],     ah, bh[0], bh[1]);
                MMA_BF16(acc[2 * p],     ah, bl[0], bl[1]);
                MMA_BF16(acc[2 * p],     al, bh[0], bh[1]);
                MMA_BF16(acc[2 * p + 1], ah, bh[2], bh[3]);
                MMA_BF16(acc[2 * p + 1], ah, bl[2], bl[3]);
                MMA_BF16(acc[2 * p + 1], al, bh[2], bh[3]);
            }
        }
    }

    // ------------------- epilogue -------------------
    const int r0 = c0 + warp * 16 + (lane >> 2);
    const int r1 = r0 + 8;
    const int cq = 2 * (lane & 3);

    if (KID == 1) {
        #pragma unroll
        for (int nt = 0; nt < 16; nt++) {
            int cl = nt * 8 + cq;
            float b0v = s_b[cl], b1v = s_b[cl + 1];
            float2 v0 = make_float2(fmaxf(acc[nt][0] + b0v, 0.f), fmaxf(acc[nt][1] + b1v, 0.f));
            float2 v1 = make_float2(fmaxf(acc[nt][2] + b0v, 0.f), fmaxf(acc[nt][3] + b1v, 0.f));
            *(float2*)&g_H1[(size_t)r0 * 256 + m0 + cl] = v0;
            *(float2*)&g_H1[(size_t)r1 * 256 + m0 + cl] = v1;
        }
    } else if (KID == 3) {
        #pragma unroll
        for (int nt = 0; nt < 16; nt++) {
            int cl = nt * 8 + cq;
            float b0v = s_b[cl], b1v = s_b[cl + 1];
            float2 v0 = make_float2(acc[nt][0] + b0v, acc[nt][1] + b1v);
            float2 v1 = make_float2(acc[nt][2] + b0v, acc[nt][3] + b1v);
            *(float2*)&g_G1[(size_t)r0 * 768 + m0 + cl] = v0;
            *(float2*)&g_G1[(size_t)r1 * 768 + m0 + cl] = v1;
        }
    } else if (KID == 4) {
        float t0 = g_tension[r0], t1 = g_tension[r1];
        #pragma unroll
        for (int nt = 0; nt < 16; nt++) {
            int cl = nt * 8 + cq;
            float b0v = s_b[cl], b1v = s_b[cl + 1];
            float w0c = s_wcol[cl], w1c = s_wcol[cl + 1];
            float2 v0 = make_float2(acc[nt][0] + b0v + t0 * w0c, acc[nt][1] + b1v + t0 * w1c);
            float2 v1 = make_float2(acc[nt][2] + b0v + t1 * w0c, acc[nt][3] + b1v + t1 * w1c);
            *(float2*)&g_G2[(size_t)r0 * 768 + m0 + cl] = v0;
            *(float2*)&g_G2[(size_t)r1 * 768 + m0 + cl] = v1;
        }
    } else {  // KID == 2
        float s0 = 0.f, s1 = 0.f;
        #pragma unroll
        for (int nt = 0; nt < 16; nt++) {
            int cl = nt * 8 + cq;
            float b0v = s_b[cl], b1v = s_b[cl + 1];
            acc[nt][0] += b0v; acc[nt][1] += b1v;
            acc[nt][2] += b0v; acc[nt][3] += b1v;
            s0 += acc[nt][0] * acc[nt][0] + acc[nt][1] * acc[nt][1];
            s1 += acc[nt][2] * acc[nt][2] + acc[nt][3] * acc[nt][3];
        }
        s0 += __shfl_xor_sync(0xffffffffu, s0, 1);
        s0 += __shfl_xor_sync(0xffffffffu, s0, 2);
        s1 += __shfl_xor_sync(0xffffffffu, s1, 1);
        s1 += __shfl_xor_sync(0xffffffffu, s1, 2);
        float t0 = s0 * 0.0078125f, t1 = s1 * 0.0078125f;
        float w0 = expf(t0), w1 = expf(t1);
        if ((lane & 3) == 0) { g_tension[r0] = t0; g_tension[r1] = t1; }
        #pragma unroll
        for (int nt = 0; nt < 16; nt++) {
            int cl = nt * 8 + cq;
            *(float2*)&g_out[(size_t)r0 * 128 + cl] = make_float2(acc[nt][0], acc[nt][1]);
            *(float2*)&g_out[(size_t)r1 * 128 + cl] = make_float2(acc[nt][2], acc[nt][3]);
        }
        // weighted col sums: reduce across rows (lanes with same lane&3)
        #pragma unroll
        for (int nt = 0; nt < 16; nt++) {
            float pw0 = w0 * acc[nt][0] + w1 * acc[nt][2];
            float pw1 = w0 * acc[nt][1] + w1 * acc[nt][3];
            pw0 += __shfl_xor_sync(0xffffffffu, pw0, 4);
            pw0 += __shfl_xor_sync(0xffffffffu, pw0, 8);
            pw0 += __shfl_xor_sync(0xffffffffu, pw0, 16);
            pw1 += __shfl_xor_sync(0xffffffffu, pw1, 4);
            pw1 += __shfl_xor_sync(0xffffffffu, pw1, 8);
            pw1 += __shfl_xor_sync(0xffffffffu, pw1, 16);
            if ((lane >> 2) == 0) {
                atomicAdd(&s_wout[nt * 8 + cq], pw0);
                atomicAdd(&s_wout[nt * 8 + cq + 1], pw1);
            }
        }
        float se = ((lane & 3) == 0) ? (w0 + w1) : 0.f;
        float st = ((lane & 3) == 0) ? (t0 + t1) : 0.f;
        #pragma unroll
        for (int o = 16; o > 0; o >>= 1) {
            se += __shfl_xor_sync(0xffffffffu, se, o);
            st += __shfl_xor_sync(0xffffffffu, st, o);
        }
        if (lane == 0) { atomicAdd(&s_scal[0], se); atomicAdd(&s_scal[1], st); }
        __syncthreads();
        if (tid < 128) atomicAdd(&g_sumexpout[tid], s_wout[tid]);
        if (tid == 0) { atomicAdd(&g_sumexp, s_scal[0]); atomicAdd(&g_sumtens, s_scal[1]); }
    }
}

// ---------------------------------------------------------------------------
// K3c: GRU gates -> newh + faction sums
// ---------------------------------------------------------------------------
__device__ __forceinline__ float sigmoidf_(float x) { return 1.f / (1.f + expf(-x)); }

__global__ void __launch_bounds__(256) k3c_gates(const float* __restrict__ hiddens,
                                                 const float* __restrict__ payoffs) {
    const int c0 = blockIdx.x * 128;
    const int j = threadIdx.x;
    const int f = c0 >> 14;
    const bool is_dc = (c0 & (FS - 1)) < DC;
    float lsum = 0.f;
    for (int ii = 0; ii < 128; ii++) {
        int i = c0 + ii;
        size_t b = (size_t)i * 768;
        float gi_r = g_G2[b + j],       gh_r = g_G1[b + j];
        float gi_z = g_G2[b + 256 + j], gh_z = g_G1[b + 256 + j];
        float gi_n = g_G2[b + 512 + j], gh_n = g_G1[b + 512 + j];
        float rg = sigmoidf_(gi_r + gh_r);
        float zg = sigmoidf_(gi_z + gh_z);
        float ng = tanhf(gi_n + rg * gh_n);
        float h = hiddens[(size_t)i * 256 + j];
        float v = (1.f - zg) * ng + zg * h;
        v *= (0.9f + 0.02f * payoffs[i]);
        v = fminf(fmaxf(v, -10.f), 10.f);
        g_newh[(size_t)i * 256 + j] = v;
        lsum += v;
    }
    atomicAdd(&g_fsum[f * 256 + j], lsum);
    if (is_dc) atomicAdd(&g_fdcsum[f * 256 + j], lsum);
}

// ---------------------------------------------------------------------------
// K4: faction means, global_op, analytic gmean, pred, avg_tension
// ---------------------------------------------------------------------------
__global__ void k4_small(const int* __restrict__ step,
                         const float* __restrict__ head_w,
                         const float* __restrict__ head_b,
                         float* __restrict__ out) {
    const int j = threadIdx.x;
    float fs[8], fm[8];
    float gop = 0.f, total = 0.f;
    #pragma unroll
    for (int f = 0; f < 8; f++) {
        fs[f] = g_fsum[f * 256 + j];
        fm[f] = fs[f] * (1.f / 16384.f);
        gop += fm[f];
        total += fs[f];
    }
    gop *= 0.125f;
    if (*step > 5) {
        #pragma unroll
        for (int f = 0; f < 8; f++) {
            float ssdc = 0.85f * g_fdcsum[f * 256 + j] + 0.15f * 4096.f * fm[f];
            total += 0.15f * (4096.f * gop - ssdc);
        }
    }
    g_gmean[j] = total * (1.f / 131072.f);
    g_globalop[j] = gop;
    #pragma unroll
    for (int f = 0; f < 8; f++) g_fmean[f * 256 + j] = fm[f];

    if (j < 128) {
        float inv = 1.0f / g_sumexp;
        float a = head_b[j];
        #pragma unroll 4
        for (int q = 0; q < 128; q++) a += head_w[(size_t)j * 128 + q] * (g_sumexpout[q] * inv);
        out[j] = a;
    }
    if (j == 0) out[128] = g_sumtens * (1.f / 131072.f);
}

// ---------------------------------------------------------------------------
// threefry2x32 partitionable: counter = (0, e), key (0,42), bits = out0^out1
// ---------------------------------------------------------------------------
__device__ __forceinline__ float threefry_normal(unsigned e) {
    unsigned x0 = 0u, x1 = e;
    const unsigned ks0 = 0u, ks1 = 42u, ks2 = 0u ^ 42u ^ 0x1BD11BDAu;
    x0 += ks0; x1 += ks1;
#define TF_ROT(v, r) (((v) << (r)) | ((v) >> (32 - (r))))
#define TF_R4(a, b, c, d)                                        \
    x0 += x1; x1 = TF_ROT(x1, a); x1 ^= x0;                      \
    x0 += x1; x1 = TF_ROT(x1, b); x1 ^= x0;                      \
    x0 += x1; x1 = TF_ROT(x1, c); x1 ^= x0;                      \
    x0 += x1; x1 = TF_ROT(x1, d); x1 ^= x0;
    TF_R4(13, 15, 26, 6);  x0 += ks1; x1 += ks2 + 1u;
    TF_R4(17, 29, 16, 24); x0 += ks2; x1 += ks0 + 2u;
    TF_R4(13, 15, 26, 6);  x0 += ks0; x1 += ks1 + 3u;
    TF_R4(17, 29, 16, 24); x0 += ks1; x1 += ks2 + 4u;
    TF_R4(13, 15, 26, 6);  x0 += ks2; x1 += ks0 + 5u;
#undef TF_R4
#undef TF_ROT
    unsigned bits = x0 ^ x1;
    unsigned fb = (bits >> 9) | 0x3F800000u;
    float f01 = __uint_as_float(fb) - 1.0f;
    const float lo = -0.99999994f;
    float u = f01 * 2.0f + lo;
    u = fmaxf(u, lo);
    return 1.4142135f * erfinvf(u);
}

// ---------------------------------------------------------------------------
// K5: faction sync + debate + coop pull + noise + clamp
// ---------------------------------------------------------------------------
__global__ void __launch_bounds__(256) k5_final(const int* __restrict__ last_action,
                                                const int* __restrict__ step,
                                                float* __restrict__ out) {
    const int i = blockIdx.x;
    const int j = threadIdx.x;
    float v = g_newh[(size_t)i * 256 + j];
    const int f = i >> 14;
    v = 0.85f * v + 0.15f * g_fmean[f * 256 + j];
    if (*step > 5 && (i & (FS - 1)) < DC)
        v = 0.85f * v + 0.15f * g_globalop[j];
    float coop = (float)last_action[i];
    v += 0.05f * coop * (g_gmean[j] - v);
    unsigned e = (unsigned)i * 256u + (unsigned)j;
    float nz = threefry_normal(e);
    v += 0.02f * (1.0f - coop) * nz;
    v = fminf(fmaxf(v, -10.f), 10.f);
    out[129 + (size_t)i * 256 + j] = v;
}

// ---------------------------------------------------------------------------
extern "C" void kernel_launch(void* const* d_in, const int* in_sizes, int n_in,
                              void* d_out, int out_size) {
    const float* x        = (const float*)d_in[0];
    const float* payoffs  = (const float*)d_in[1];
    const int*   last_act = (const int*)d_in[2];
    const int*   step     = (const int*)d_in[3];
    const float* hiddens  = (const float*)d_in[4];
    const float* a_w1 = (const float*)d_in[5];
    const float* a_b1 = (const float*)d_in[6];
    const float* a_w2 = (const float*)d_in[7];
    const float* a_b2 = (const float*)d_in[8];
    const float* g_w1 = (const float*)d_in[9];
    const float* g_b1 = (const float*)d_in[10];
    const float* g_w2 = (const float*)d_in[11];
    const float* g_b2 = (const float*)d_in[12];
    const float* gru_wih = (const float*)d_in[13];
    const float* gru_whh = (const float*)d_in[14];
    const float* gru_bih = (const float*)d_in[15];
    const float* gru_bhh = (const float*)d_in[16];
    const float* head_w  = (const float*)d_in[17];
    const float* head_b  = (const float*)d_in[18];
    float* out = (float*)d_out;

    k0_init<<<1, 256>>>(x, a_w1, a_b1, g_w1, g_b1);
    gemm_mma<1><<<dim3(NCELLS / 128, 2), 256>>>(hiddens, a_w1, g_w1, nullptr, nullptr);
    gemm_mma<2><<<dim3(NCELLS / 128, 1), 256>>>(nullptr, a_w2, g_w2, a_b2, g_b2);
    gemm_mma<3><<<dim3(NCELLS / 128, 6), 256>>>(hiddens, gru_whh, nullptr, gru_bhh, nullptr);
    gemm_mma<4><<<dim3(NCELLS / 128, 6), 256>>>(nullptr, gru_wih, nullptr, gru_bih, nullptr);
    k3c_gates<<<NCELLS / 128, 256>>>(hiddens, payoffs);
    k4_small<<<1, 256>>>(step, head_w, head_b, out);
    k5_final<<<NCELLS, 256>>>(last_act, step, out);
}

// round 12
// speedup vs baseline: 2.8218x; 2.0907x over previous
#include <cuda_runtime.h>
#include <cuda_fp16.h>
#include <math.h>
#include <cstdint>

// ---------------------------------------------------------------------------
// PrisonerDilemmaEngine — R8: fp16 hi/lo 3-term mma.sync, cp.async double-buffer,
// fused GRU-gates GEMM, G in f32, tension-column bug fixed.
// ---------------------------------------------------------------------------

#define NCELLS 131072
#define FS     16384
#define DC     4096

// hi/lo f16 scratch (activations)
__device__ __align__(16) __half g_hid_hi[(size_t)NCELLS * 256];
__device__ __align__(16) __half g_hid_lo[(size_t)NCELLS * 256];
__device__ __align__(16) __half g_H1_hi[(size_t)NCELLS * 256];
__device__ __align__(16) __half g_H1_lo[(size_t)NCELLS * 256];
__device__ __align__(16) __half g_out_hi[(size_t)NCELLS * 128];
__device__ __align__(16) __half g_out_lo[(size_t)NCELLS * 128];
// hi/lo f16 weights
__device__ __align__(16) __half g_w1_hi[256 * 256];
__device__ __align__(16) __half g_w1_lo[256 * 256];
__device__ __align__(16) __half g_w2_hi[128 * 256];
__device__ __align__(16) __half g_w2_lo[128 * 256];
__device__ __align__(16) __half g_gw_hi[1024 * 384];
__device__ __align__(16) __half g_gw_lo[1024 * 384];
__device__ float g_gb[1024];
__device__ float g_wcol2[1024];
// f32 scratch
__device__ __align__(16) float g_G[(size_t)NCELLS * 1024];   // [rsum|zsum|gi_n|gh_n]
__device__ __align__(16) float g_newh[(size_t)NCELLS * 256];
__device__ __align__(16) float g_tension[NCELLS];
__device__ float g_xwb[256];
__device__ float g_fsum[2048];
__device__ float g_fdcsum[2048];
__device__ float g_fmean[2048];
__device__ float g_globalop[256];
__device__ float g_gmean[256];
__device__ float g_sumexp;
__device__ float g_sumtens;
__device__ float g_sumexpout[128];

// ---------------------------------------------------------------------------
// PTX helpers
// ---------------------------------------------------------------------------
__device__ __forceinline__ unsigned sptr(const void* p) {
    return (unsigned)__cvta_generic_to_shared(p);
}
#define CP16(dst, src) \
    asm volatile("cp.async.ca.shared.global [%0], [%1], 16;" :: "r"(dst), "l"(src))
#define CPCOMMIT() asm volatile("cp.async.commit_group;" ::: "memory")
#define CPWAIT(n)  asm volatile("cp.async.wait_group %0;" :: "n"(n) : "memory")
#define LDSM4(r0, r1, r2, r3, addr)                                              \
    asm volatile("ldmatrix.sync.aligned.m8n8.x4.shared.b16 {%0,%1,%2,%3}, [%4];" \
                 : "=r"(r0), "=r"(r1), "=r"(r2), "=r"(r3) : "r"(addr))
#define MMA_F16(d, a0_, a1_, a2_, a3_, b0_, b1_)                             \
    asm volatile("mma.sync.aligned.m16n8k16.row.col.f32.f16.f16.f32 "        \
                 "{%0,%1,%2,%3},{%4,%5,%6,%7},{%8,%9},{%0,%1,%2,%3};"        \
                 : "+f"(d[0]), "+f"(d[1]), "+f"(d[2]), "+f"(d[3])            \
                 : "r"(a0_), "r"(a1_), "r"(a2_), "r"(a3_),                   \
                   "r"(b0_), "r"(b1_))

__device__ __forceinline__ void split_h2(float a, float b, __half2& hi, __half2& lo) {
    __half ha = __float2half_rn(a), hb = __float2half_rn(b);
    hi = __halves2half2(ha, hb);
    lo = __halves2half2(__float2half_rn(a - __half2float(ha)),
                        __float2half_rn(b - __half2float(hb)));
}

// ---------------------------------------------------------------------------
// K0: zero accumulators + xwb
// ---------------------------------------------------------------------------
__global__ void k0_init(const float* __restrict__ x,
                        const float* __restrict__ a_w1, const float* __restrict__ a_b1,
                        const float* __restrict__ g_w1, const float* __restrict__ g_b1) {
    int tid = threadIdx.x;
    if (tid == 0) { g_sumexp = 0.f; g_sumtens = 0.f; }
    if (tid < 128) g_sumexpout[tid] = 0.f;
    for (int k = tid; k < 2048; k += 256) { g_fsum[k] = 0.f; g_fdcsum[k] = 0.f; }
    int r = tid;
    const float* w = (r < 128) ? (a_w1 + (size_t)r * 384) : (g_w1 + (size_t)(r - 128) * 384);
    float s = (r < 128) ? a_b1[r] : g_b1[r - 128];
    #pragma unroll 4
    for (int k = 0; k < 128; k++) s += x[k] * w[k];
    g_xwb[r] = s;
}

// ---------------------------------------------------------------------------
// kconv: weights -> hi/lo f16; gates bias + tension column (FIXED: all r<768)
// ranges: w1 65536 | w2 32768 | gw 393216 | gb/wcol 1024  (total 492544)
// ---------------------------------------------------------------------------
__global__ void kconv(const float* __restrict__ a_w1, const float* __restrict__ g_w1,
                      const float* __restrict__ a_w2, const float* __restrict__ g_w2,
                      const float* __restrict__ wih,  const float* __restrict__ whh,
                      const float* __restrict__ bih,  const float* __restrict__ bhh) {
    int t = blockIdx.x * 256 + threadIdx.x;
    if (t < 65536) {
        int r = t >> 8, k = t & 255;
        float v = (r < 128) ? a_w1[(size_t)r * 384 + 128 + k]
                            : g_w1[(size_t)(r - 128) * 384 + 128 + k];
        __half h = __float2half_rn(v);
        g_w1_hi[t] = h;
        g_w1_lo[t] = __float2half_rn(v - __half2float(h));
        return;
    }
    t -= 65536;
    if (t < 32768) {
        int r = t >> 8, k = t & 255;
        float v = (k < 128) ? a_w2[(size_t)r * 128 + k] : -g_w2[(size_t)r * 128 + (k - 128)];
        __half h = __float2half_rn(v);
        g_w2_hi[t] = h;
        g_w2_lo[t] = __float2half_rn(v - __half2float(h));
        return;
    }
    t -= 32768;
    if (t < 393216) {
        int r = t / 384, k = t - r * 384;
        float v = 0.f;
        if (r < 512)       v = (k < 128) ? wih[(size_t)r * 129 + k] : whh[(size_t)r * 256 + (k - 128)];
        else if (r < 768)  { if (k < 128) v = wih[(size_t)r * 129 + k]; }
        else               { if (k < 256) v = whh[(size_t)(r - 256) * 256 + k]; }
        __half h = __float2half_rn(v);
        g_gw_hi[t] = h;
        g_gw_lo[t] = __float2half_rn(v - __half2float(h));
        return;
    }
    t -= 393216;
    if (t < 1024) {
        int r = t;
        float b;
        if (r < 512)      b = bih[r] + bhh[r];
        else if (r < 768) b = bih[r];
        else              b = bhh[r - 256];
        g_gb[r] = b;
        g_wcol2[r] = (r < 768) ? wih[(size_t)r * 129 + 128] : 0.f;   // FIX: r,z too
    }
}

// ---------------------------------------------------------------------------
// khh: hiddens f32 -> hi/lo f16 (8 elems/thread)
// ---------------------------------------------------------------------------
__global__ void __launch_bounds__(256) khh(const float* __restrict__ hiddens) {
    size_t base = ((size_t)blockIdx.x * 256 + threadIdx.x) * 8;
    float4 a = *(const float4*)(hiddens + base);
    float4 b = *(const float4*)(hiddens + base + 4);
    __half2 hi[4], lo[4];
    split_h2(a.x, a.y, hi[0], lo[0]);
    split_h2(a.z, a.w, hi[1], lo[1]);
    split_h2(b.x, b.y, hi[2], lo[2]);
    split_h2(b.z, b.w, hi[3], lo[3]);
    *(uint4*)(g_hid_hi + base) = *(uint4*)hi;
    *(uint4*)(g_hid_lo + base) = *(uint4*)lo;
}

// ---------------------------------------------------------------------------
// stage loader: A/B tiles 128x32 f16 hi+lo, pure cp.async (8x 16B per thread)
// smem layout per stage (halfs): [0]=Ah [5120]=Al [10240]=Bh [15360]=Bl
// tile stride 40 halfs/row
// ---------------------------------------------------------------------------
#define TILEH 5120
#define STAGEH 20480

template <int KID>
__device__ __forceinline__ void load_stage(__half* dyn, int stage, int k0,
                                           int c0, int m0, int grp) {
    const int tid = threadIdx.x;
    __half* base = dyn + stage * STAGEH;
    #pragma unroll
    for (int i = 0; i < 2; i++) {
        int q = tid + 256 * i;
        int row = q >> 2, c8 = (q & 3) * 8;
        const __half *sh, *sl;
        if (KID == 1) {
            size_t off = (size_t)(c0 + row) * 256 + k0 + c8;
            sh = g_hid_hi + off; sl = g_hid_lo + off;
        } else if (KID == 2) {
            size_t off = (size_t)(c0 + row) * 256 + k0 + c8;
            sh = g_H1_hi + off; sl = g_H1_lo + off;
        } else {
            int kk = k0 + c8;
            if (grp < 4) {
                if (kk < 128) { size_t off = (size_t)(c0 + row) * 128 + kk; sh = g_out_hi + off; sl = g_out_lo + off; }
                else          { size_t off = (size_t)(c0 + row) * 256 + (kk - 128); sh = g_hid_hi + off; sl = g_hid_lo + off; }
            } else if (grp < 6) { size_t off = (size_t)(c0 + row) * 128 + kk; sh = g_out_hi + off; sl = g_out_lo + off; }
            else                { size_t off = (size_t)(c0 + row) * 256 + kk; sh = g_hid_hi + off; sl = g_hid_lo + off; }
        }
        __half* d = base + row * 40 + c8;
        CP16(sptr(d), sh);
        CP16(sptr(d + TILEH), sl);
    }
    #pragma unroll
    for (int i = 0; i < 2; i++) {
        int q = tid + 256 * i;
        int row = q >> 2, c8 = (q & 3) * 8;
        size_t off;
        const __half *sh, *sl;
        if (KID == 1)      { off = (size_t)(m0 + row) * 256 + k0 + c8; sh = g_w1_hi + off; sl = g_w1_lo + off; }
        else if (KID == 2) { off = (size_t)row * 256 + k0 + c8;        sh = g_w2_hi + off; sl = g_w2_lo + off; }
        else               { off = (size_t)(m0 + row) * 384 + k0 + c8; sh = g_gw_hi + off; sl = g_gw_lo + off; }
        __half* d = base + 2 * TILEH + row * 40 + c8;
        CP16(sptr(d), sh);
        CP16(sptr(d + TILEH), sl);
    }
}

// ---------------------------------------------------------------------------
// Unified hi/lo f16 GEMM: tile 128 cells x 128 cols, 8 warps (4x2), warp 32x64,
// K-chunk 32, double-buffered cp.async, 3-term MMA.
// KID: 1=layer1(relu->H1 hi/lo)  2=layer2(out hi/lo,tension,softmax)  3=gates->G f32
// ---------------------------------------------------------------------------
template <int KID>
__global__ void __launch_bounds__(256, 2) gemm_hl(const float* __restrict__ B0,
                                                  const float* __restrict__ B1) {
    extern __shared__ __half dyn[];
    __shared__ float s_b[128], s_aux[128], s_row[128], s_w[128], s_wout[128];

    const int tid = threadIdx.x, lane = tid & 31, warp = tid >> 5;
    const int rw = warp & 3, cw = warp >> 2;
    const int m0 = blockIdx.x * 128, c0 = blockIdx.y * 128;
    const int grp = (KID == 3) ? blockIdx.x : 0;
    int KD = 256;
    if (KID == 3) KD = (grp < 4) ? 384 : ((grp < 6) ? 128 : 256);
    const int NC = KD >> 5;

    if (tid < 128) {
        if (KID == 1) s_b[tid] = g_xwb[m0 + tid];
        if (KID == 2) { s_b[tid] = B0[tid] - B1[tid]; s_row[tid] = 0.f; s_wout[tid] = 0.f; }
        if (KID == 3) {
            s_b[tid] = g_gb[m0 + tid];
            s_w[tid] = g_wcol2[m0 + tid];
            s_aux[tid] = g_tension[c0 + tid];
        }
    }

    float acc[2][8][4];
    #pragma unroll
    for (int mt = 0; mt < 2; mt++)
        #pragma unroll
        for (int nq = 0; nq < 8; nq++)
            #pragma unroll
            for (int e = 0; e < 4; e++) acc[mt][nq][e] = 0.f;

    load_stage<KID>(dyn, 0, 0, c0, m0, grp);
    CPCOMMIT();

    const int a_r = (lane & 7) + ((lane >> 3) & 1) * 8;
    const int a_c = ((lane >> 3) & 2) << 2;
    const int b_r = (lane & 7) + (((lane >> 3) & 2) << 2);
    const int b_c = ((lane >> 3) & 1) * 8;

    for (int c = 0; c < NC; c++) {
        if (c + 1 < NC) {
            load_stage<KID>(dyn, (c + 1) & 1, (c + 1) * 32, c0, m0, grp);
            CPCOMMIT();
            CPWAIT(1);
        } else {
            CPWAIT(0);
        }
        __syncthreads();
        __half* st = dyn + (c & 1) * STAGEH;
        #pragma unroll
        for (int kh = 0; kh < 2; kh++) {
            unsigned ah[2][4], al[2][4];
            #pragma unroll
            for (int mt = 0; mt < 2; mt++) {
                __half* ap = st + (rw * 32 + mt * 16 + a_r) * 40 + kh * 16 + a_c;
                LDSM4(ah[mt][0], ah[mt][1], ah[mt][2], ah[mt][3], sptr(ap));
                LDSM4(al[mt][0], al[mt][1], al[mt][2], al[mt][3], sptr(ap + TILEH));
            }
            #pragma unroll
            for (int nt = 0; nt < 4; nt++) {
                unsigned bh[4], bl[4];
                __half* bp = st + 2 * TILEH + (cw * 64 + nt * 16 + b_r) * 40 + kh * 16 + b_c;
                LDSM4(bh[0], bh[1], bh[2], bh[3], sptr(bp));
                LDSM4(bl[0], bl[1], bl[2], bl[3], sptr(bp + TILEH));
                #pragma unroll
                for (int mt = 0; mt < 2; mt++) {
                    MMA_F16(acc[mt][2 * nt], ah[mt][0], ah[mt][1], ah[mt][2], ah[mt][3], bh[0], bh[1]);
                    MMA_F16(acc[mt][2 * nt], al[mt][0], al[mt][1], al[mt][2], al[mt][3], bh[0], bh[1]);
                    MMA_F16(acc[mt][2 * nt], ah[mt][0], ah[mt][1], ah[mt][2], ah[mt][3], bl[0], bl[1]);
                    MMA_F16(acc[mt][2 * nt + 1], ah[mt][0], ah[mt][1], ah[mt][2], ah[mt][3], bh[2], bh[3]);
                    MMA_F16(acc[mt][2 * nt + 1], al[mt][0], al[mt][1], al[mt][2], al[mt][3], bh[2], bh[3]);
                    MMA_F16(acc[mt][2 * nt + 1], ah[mt][0], ah[mt][1], ah[mt][2], ah[mt][3], bl[2], bl[3]);
                }
            }
        }
        __syncthreads();
    }

    // ------------------- epilogue -------------------
    const int rowb = c0 + rw * 32 + (lane >> 2);
    const int colb = cw * 64 + 2 * (lane & 3);

    if (KID == 1) {
        #pragma unroll
        for (int mt = 0; mt < 2; mt++) {
            int row0 = rowb + mt * 16, row1 = row0 + 8;
            #pragma unroll
            for (int nq = 0; nq < 8; nq++) {
                int col = colb + nq * 8;
                float b0v = s_b[col], b1v = s_b[col + 1];
                __half2 hi, lo;
                split_h2(fmaxf(acc[mt][nq][0] + b0v, 0.f), fmaxf(acc[mt][nq][1] + b1v, 0.f), hi, lo);
                *(__half2*)&g_H1_hi[(size_t)row0 * 256 + m0 + col] = hi;
                *(__half2*)&g_H1_lo[(size_t)row0 * 256 + m0 + col] = lo;
                split_h2(fmaxf(acc[mt][nq][2] + b0v, 0.f), fmaxf(acc[mt][nq][3] + b1v, 0.f), hi, lo);
                *(__half2*)&g_H1_hi[(size_t)row1 * 256 + m0 + col] = hi;
                *(__half2*)&g_H1_lo[(size_t)row1 * 256 + m0 + col] = lo;
            }
        }
    } else if (KID == 3) {
        #pragma unroll
        for (int mt = 0; mt < 2; mt++) {
            int row0 = rowb + mt * 16, row1 = row0 + 8;
            float t0 = s_aux[row0 - c0], t1 = s_aux[row1 - c0];
            #pragma unroll
            for (int nq = 0; nq < 8; nq++) {
                int col = colb + nq * 8;
                float b0v = s_b[col], b1v = s_b[col + 1];
                float w0c = s_w[col], w1c = s_w[col + 1];
                *(float2*)&g_G[(size_t)row0 * 1024 + m0 + col] =
                    make_float2(acc[mt][nq][0] + b0v + t0 * w0c, acc[mt][nq][1] + b1v + t0 * w1c);
                *(float2*)&g_G[(size_t)row1 * 1024 + m0 + col] =
                    make_float2(acc[mt][nq][2] + b0v + t1 * w0c, acc[mt][nq][3] + b1v + t1 * w1c);
            }
        }
    } else {  // KID == 2
        float ss0[2] = {0.f, 0.f}, ss1[2] = {0.f, 0.f};
        #pragma unroll
        for (int mt = 0; mt < 2; mt++) {
            int row0 = rowb + mt * 16, row1 = row0 + 8;
            #pragma unroll
            for (int nq = 0; nq < 8; nq++) {
                int col = colb + nq * 8;
                float b0v = s_b[col], b1v = s_b[col + 1];
                float v0 = acc[mt][nq][0] + b0v, v1 = acc[mt][nq][1] + b1v;
                float v2 = acc[mt][nq][2] + b0v, v3 = acc[mt][nq][3] + b1v;
                acc[mt][nq][0] = v0; acc[mt][nq][1] = v1;
                acc[mt][nq][2] = v2; acc[mt][nq][3] = v3;
                ss0[mt] += v0 * v0 + v1 * v1;
                ss1[mt] += v2 * v2 + v3 * v3;
                __half2 hi, lo;
                split_h2(v0, v1, hi, lo);
                *(__half2*)&g_out_hi[(size_t)row0 * 128 + col] = hi;
                *(__half2*)&g_out_lo[(size_t)row0 * 128 + col] = lo;
                split_h2(v2, v3, hi, lo);
                *(__half2*)&g_out_hi[(size_t)row1 * 128 + col] = hi;
                *(__half2*)&g_out_lo[(size_t)row1 * 128 + col] = lo;
            }
        }
        #pragma unroll
        for (int mt = 0; mt < 2; mt++) {
            #pragma unroll
            for (int o = 1; o <= 2; o <<= 1) {
                ss0[mt] += __shfl_xor_sync(0xffffffffu, ss0[mt], o);
                ss1[mt] += __shfl_xor_sync(0xffffffffu, ss1[mt], o);
            }
            if ((lane & 3) == 0) {
                atomicAdd(&s_row[rw * 32 + mt * 16 + (lane >> 2)], ss0[mt]);
                atomicAdd(&s_row[rw * 32 + mt * 16 + (lane >> 2) + 8], ss1[mt]);
            }
        }
        __syncthreads();
        if (tid < 128) {
            float t = s_row[tid] * 0.0078125f;
            g_tension[c0 + tid] = t;
            float w = __expf(t);
            s_w[tid] = w;
            float se = w, st = t;
            #pragma unroll
            for (int o = 16; o > 0; o >>= 1) {
                se += __shfl_xor_sync(0xffffffffu, se, o);
                st += __shfl_xor_sync(0xffffffffu, st, o);
            }
            if (lane == 0) { atomicAdd(&g_sumexp, se); atomicAdd(&g_sumtens, st); }
        }
        __syncthreads();
        float pw[16];
        #pragma unroll
        for (int j = 0; j < 16; j++) pw[j] = 0.f;
        #pragma unroll
        for (int mt = 0; mt < 2; mt++) {
            int rl0 = rw * 32 + mt * 16 + (lane >> 2);
            float w0 = s_w[rl0], w1 = s_w[rl0 + 8];
            #pragma unroll
            for (int nq = 0; nq < 8; nq++) {
                pw[2 * nq]     += w0 * acc[mt][nq][0] + w1 * acc[mt][nq][2];
                pw[2 * nq + 1] += w0 * acc[mt][nq][1] + w1 * acc[mt][nq][3];
            }
        }
        #pragma unroll
        for (int j = 0; j < 16; j++)
            #pragma unroll
            for (int o = 4; o <= 16; o <<= 1) pw[j] += __shfl_xor_sync(0xffffffffu, pw[j], o);
        if (lane < 4) {
            #pragma unroll
            for (int nq = 0; nq < 8; nq++) {
                atomicAdd(&s_wout[cw * 64 + nq * 8 + 2 * lane], pw[2 * nq]);
                atomicAdd(&s_wout[cw * 64 + nq * 8 + 2 * lane + 1], pw[2 * nq + 1]);
            }
        }
        __syncthreads();
        if (tid < 128) atomicAdd(&g_sumexpout[tid], s_wout[tid]);
    }
}

// ---------------------------------------------------------------------------
// k3c: GRU gates from G (f32) -> newh + faction sums
// ---------------------------------------------------------------------------
__device__ __forceinline__ float sigmoidf_(float x) { return 1.f / (1.f + __expf(-x)); }

__global__ void __launch_bounds__(256) k3c_gates(const float* __restrict__ hiddens,
                                                 const float* __restrict__ payoffs) {
    const int c0 = blockIdx.x * 128;
    const int j = threadIdx.x;
    const int f = c0 >> 14;
    const bool is_dc = (c0 & (FS - 1)) < DC;
    float lsum = 0.f;
    for (int ii = 0; ii < 128; ii++) {
        int i = c0 + ii;
        size_t b = (size_t)i * 1024;
        float gr  = g_G[b + j];
        float gz  = g_G[b + 256 + j];
        float gin = g_G[b + 512 + j];
        float ghn = g_G[b + 768 + j];
        float rg = sigmoidf_(gr);
        float zg = sigmoidf_(gz);
        float ng = tanhf(gin + rg * ghn);
        float h = hiddens[(size_t)i * 256 + j];
        float v = (1.f - zg) * ng + zg * h;
        v *= (0.9f + 0.02f * payoffs[i]);
        v = fminf(fmaxf(v, -10.f), 10.f);
        g_newh[(size_t)i * 256 + j] = v;
        lsum += v;
    }
    atomicAdd(&g_fsum[f * 256 + j], lsum);
    if (is_dc) atomicAdd(&g_fdcsum[f * 256 + j], lsum);
}

// ---------------------------------------------------------------------------
// k4: faction means, global_op, analytic gmean, pred, avg_tension
// ---------------------------------------------------------------------------
__global__ void k4_small(const int* __restrict__ step,
                         const float* __restrict__ head_w,
                         const float* __restrict__ head_b,
                         float* __restrict__ out) {
    const int j = threadIdx.x;
    float fs[8], fm[8];
    float gop = 0.f, total = 0.f;
    #pragma unroll
    for (int f = 0; f < 8; f++) {
        fs[f] = g_fsum[f * 256 + j];
        fm[f] = fs[f] * (1.f / 16384.f);
        gop += fm[f];
        total += fs[f];
    }
    gop *= 0.125f;
    if (*step > 5) {
        #pragma unroll
        for (int f = 0; f < 8; f++) {
            float ssdc = 0.85f * g_fdcsum[f * 256 + j] + 0.15f * 4096.f * fm[f];
            total += 0.15f * (4096.f * gop - ssdc);
        }
    }
    g_gmean[j] = total * (1.f / 131072.f);
    g_globalop[j] = gop;
    #pragma unroll
    for (int f = 0; f < 8; f++) g_fmean[f * 256 + j] = fm[f];

    if (j < 128) {
        float inv = 1.0f / g_sumexp;
        float a = head_b[j];
        #pragma unroll 4
        for (int q = 0; q < 128; q++) a += head_w[(size_t)j * 128 + q] * (g_sumexpout[q] * inv);
        out[j] = a;
    }
    if (j == 0) out[128] = g_sumtens * (1.f / 131072.f);
}

// ---------------------------------------------------------------------------
// threefry2x32 partitionable: counter (0,e), key (0,42), bits = out0^out1
// ---------------------------------------------------------------------------
__device__ __forceinline__ float threefry_normal(unsigned e) {
    unsigned x0 = 0u, x1 = e;
    const unsigned ks0 = 0u, ks1 = 42u, ks2 = 0u ^ 42u ^ 0x1BD11BDAu;
    x0 += ks0; x1 += ks1;
#define TF_ROT(v, r) (((v) << (r)) | ((v) >> (32 - (r))))
#define TF_R4(a, b, c, d)                                        \
    x0 += x1; x1 = TF_ROT(x1, a); x1 ^= x0;                      \
    x0 += x1; x1 = TF_ROT(x1, b); x1 ^= x0;                      \
    x0 += x1; x1 = TF_ROT(x1, c); x1 ^= x0;                      \
    x0 += x1; x1 = TF_ROT(x1, d); x1 ^= x0;
    TF_R4(13, 15, 26, 6);  x0 += ks1; x1 += ks2 + 1u;
    TF_R4(17, 29, 16, 24); x0 += ks2; x1 += ks0 + 2u;
    TF_R4(13, 15, 26, 6);  x0 += ks0; x1 += ks1 + 3u;
    TF_R4(17, 29, 16, 24); x0 += ks1; x1 += ks2 + 4u;
    TF_R4(13, 15, 26, 6);  x0 += ks2; x1 += ks0 + 5u;
#undef TF_R4
#undef TF_ROT
    unsigned bits = x0 ^ x1;
    unsigned fb = (bits >> 9) | 0x3F800000u;
    float f01 = __uint_as_float(fb) - 1.0f;
    const float lo = -0.99999994f;
    float u = f01 * 2.0f + lo;
    u = fmaxf(u, lo);
    return 1.4142135f * erfinvf(u);
}

// ---------------------------------------------------------------------------
// k5: faction sync + debate + coop pull + noise + clamp
// ---------------------------------------------------------------------------
__global__ void __launch_bounds__(256) k5_final(const int* __restrict__ last_action,
                                                const int* __restrict__ step,
                                                float* __restrict__ out) {
    const int i = blockIdx.x;
    const int j = threadIdx.x;
    float v = g_newh[(size_t)i * 256 + j];
    const int f = i >> 14;
    v = 0.85f * v + 0.15f * g_fmean[f * 256 + j];
    if (*step > 5 && (i & (FS - 1)) < DC)
        v = 0.85f * v + 0.15f * g_globalop[j];
    const int act = last_action[i];
    if (act != 0) {
        v += 0.05f * (g_gmean[j] - v);
    } else {
        unsigned e = (unsigned)i * 256u + (unsigned)j;
        v += 0.02f * threefry_normal(e);
    }
    v = fminf(fmaxf(v, -10.f), 10.f);
    out[129 + (size_t)i * 256 + j] = v;
}

// ---------------------------------------------------------------------------
#define SMEM_DYN (2 * STAGEH * 2)   // 2 stages * 20480 halfs * 2 B = 81920 B

extern "C" void kernel_launch(void* const* d_in, const int* in_sizes, int n_in,
                              void* d_out, int out_size) {
    const float* x        = (const float*)d_in[0];
    const float* payoffs  = (const float*)d_in[1];
    const int*   last_act = (const int*)d_in[2];
    const int*   step     = (const int*)d_in[3];
    const float* hiddens  = (const float*)d_in[4];
    const float* a_w1 = (const float*)d_in[5];
    const float* a_b1 = (const float*)d_in[6];
    const float* a_w2 = (const float*)d_in[7];
    const float* a_b2 = (const float*)d_in[8];
    const float* g_w1 = (const float*)d_in[9];
    const float* g_b1 = (const float*)d_in[10];
    const float* g_w2 = (const float*)d_in[11];
    const float* g_b2 = (const float*)d_in[12];
    const float* gru_wih = (const float*)d_in[13];
    const float* gru_whh = (const float*)d_in[14];
    const float* gru_bih = (const float*)d_in[15];
    const float* gru_bhh = (const float*)d_in[16];
    const float* head_w  = (const float*)d_in[17];
    const float* head_b  = (const float*)d_in[18];
    float* out = (float*)d_out;

    cudaFuncSetAttribute(gemm_hl<1>, cudaFuncAttributeMaxDynamicSharedMemorySize, SMEM_DYN);
    cudaFuncSetAttribute(gemm_hl<2>, cudaFuncAttributeMaxDynamicSharedMemorySize, SMEM_DYN);
    cudaFuncSetAttribute(gemm_hl<3>, cudaFuncAttributeMaxDynamicSharedMemorySize, SMEM_DYN);

    k0_init<<<1, 256>>>(x, a_w1, a_b1, g_w1, g_b1);
    kconv<<<1924, 256>>>(a_w1, g_w1, a_w2, g_w2, gru_wih, gru_whh, gru_bih, gru_bhh);
    khh<<<NCELLS * 256 / (256 * 8), 256>>>(hiddens);
    gemm_hl<1><<<dim3(2, NCELLS / 128), 256, SMEM_DYN>>>(nullptr, nullptr);
    gemm_hl<2><<<dim3(1, NCELLS / 128), 256, SMEM_DYN>>>(a_b2, g_b2);
    gemm_hl<3><<<dim3(8, NCELLS / 128), 256, SMEM_DYN>>>(nullptr, nullptr);
    k3c_gates<<<NCELLS / 128, 256>>>(hiddens, payoffs);
    k4_small<<<1, 256>>>(step, head_w, head_b, out);
    k5_final<<<NCELLS, 256>>>(last_act, step, out);
}